// round 1
// baseline (speedup 1.0000x reference)
#include <cuda_runtime.h>
#include <cstdint>
#include <cstddef>

#define NHEAD 8
#define HID 512
#define DK 64
#define SEQ 1024
#define BATCH 4
#define TOK 4096          // BATCH*SEQ
#define WIN 34            // band width (W+1)
#define KDIM 512
#define BM 128
#define BN 128
#define BKT 16

// ---------------- scratch (static device arrays; no allocations) ----------------
__device__ float g_st  [2ull * TOK * HID];        // current fwd/bwd state
__device__ float g_qkv [2ull * TOK * 3 * HID];    // fused q|k|v
__device__ float g_attn[2ull * TOK * HID];        // attention output
__device__ float g_y   [2ull * TOK * HID];        // branch activations
__device__ float g_proj[2ull * TOK * 2 * HID];    // highway projections

// ---------------- f32x2 helpers (Blackwell packed fp32) ----------------
__device__ __forceinline__ unsigned long long pack2(float x, float y) {
    unsigned long long r;
    asm("mov.b64 %0, {%1, %2};" : "=l"(r) : "r"(__float_as_uint(x)), "r"(__float_as_uint(y)));
    return r;
}
__device__ __forceinline__ unsigned long long ffma2(unsigned long long a,
                                                    unsigned long long b,
                                                    unsigned long long c) {
    unsigned long long d;
    asm("fma.rn.f32x2 %0, %1, %2, %3;" : "=l"(d) : "l"(a), "l"(b), "l"(c));
    return d;
}
__device__ __forceinline__ float2 unpack2(unsigned long long a) {
    unsigned lo, hi;
    asm("mov.b64 {%0, %1}, %2;" : "=r"(lo), "=r"(hi) : "l"(a));
    return make_float2(__uint_as_float(lo), __uint_as_float(hi));
}

// ---------------- SGEMM: C[M,N] = A[M,K] @ B[N,K]^T + bias ----------------
// grid: (N/BN, M/BM, 2[dir]); 256 threads; K = 512 fixed; M = 4096 fixed.
__global__ __launch_bounds__(256, 2)
void sgemm_bias(const float* __restrict__ A, const float* __restrict__ Bw,
                const float* __restrict__ bias, float* __restrict__ C,
                int N, size_t sA, size_t sB, size_t sbias, size_t sC)
{
    const int dir = blockIdx.z;
    A += (size_t)dir * sA;
    Bw += (size_t)dir * sB;
    bias += (size_t)dir * sbias;
    C += (size_t)dir * sC;

    const int bm = blockIdx.y * BM;
    const int bn = blockIdx.x * BN;

    __shared__ float As[BKT][BM];
    __shared__ float Bs[BKT][BN];

    const int tid = threadIdx.x;
    const int tx = tid & 15;   // N tile coord
    const int ty = tid >> 4;   // M tile coord

    unsigned long long acc[8][4];
#pragma unroll
    for (int i = 0; i < 8; i++)
#pragma unroll
        for (int j = 0; j < 4; j++) acc[i][j] = 0ull;

    const int lrow = tid >> 2;          // 0..63
    const int lkq  = (tid & 3) * 4;     // 0,4,8,12

    const float* Aptr = A + (size_t)(bm + lrow) * KDIM + lkq;
    const float* Bptr = Bw + (size_t)(bn + lrow) * KDIM + lkq;

#pragma unroll 1
    for (int k0 = 0; k0 < KDIM; k0 += BKT) {
        float4 a0 = *(const float4*)(Aptr + k0);
        float4 a1 = *(const float4*)(Aptr + (size_t)64 * KDIM + k0);
        float4 b0 = *(const float4*)(Bptr + k0);
        float4 b1 = *(const float4*)(Bptr + (size_t)64 * KDIM + k0);

        As[lkq + 0][lrow] = a0.x; As[lkq + 1][lrow] = a0.y;
        As[lkq + 2][lrow] = a0.z; As[lkq + 3][lrow] = a0.w;
        As[lkq + 0][lrow + 64] = a1.x; As[lkq + 1][lrow + 64] = a1.y;
        As[lkq + 2][lrow + 64] = a1.z; As[lkq + 3][lrow + 64] = a1.w;

        Bs[lkq + 0][lrow] = b0.x; Bs[lkq + 1][lrow] = b0.y;
        Bs[lkq + 2][lrow] = b0.z; Bs[lkq + 3][lrow] = b0.w;
        Bs[lkq + 0][lrow + 64] = b1.x; Bs[lkq + 1][lrow + 64] = b1.y;
        Bs[lkq + 2][lrow + 64] = b1.z; Bs[lkq + 3][lrow + 64] = b1.w;

        __syncthreads();

#pragma unroll
        for (int kk = 0; kk < BKT; kk++) {
            float4 ra0 = *(const float4*)&As[kk][ty * 8];
            float4 ra1 = *(const float4*)&As[kk][ty * 8 + 4];
            unsigned long long rb[4];
#pragma unroll
            for (int j = 0; j < 4; j++)
                rb[j] = *(const unsigned long long*)&Bs[kk][tx * 8 + 2 * j];

            unsigned long long rd[8];
            rd[0] = pack2(ra0.x, ra0.x); rd[1] = pack2(ra0.y, ra0.y);
            rd[2] = pack2(ra0.z, ra0.z); rd[3] = pack2(ra0.w, ra0.w);
            rd[4] = pack2(ra1.x, ra1.x); rd[5] = pack2(ra1.y, ra1.y);
            rd[6] = pack2(ra1.z, ra1.z); rd[7] = pack2(ra1.w, ra1.w);

#pragma unroll
            for (int i = 0; i < 8; i++)
#pragma unroll
                for (int j = 0; j < 4; j++)
                    acc[i][j] = ffma2(rd[i], rb[j], acc[i][j]);
        }
        __syncthreads();
    }

    float bv[8];
#pragma unroll
    for (int j = 0; j < 8; j++) bv[j] = bias[bn + tx * 8 + j];

#pragma unroll
    for (int i = 0; i < 8; i++) {
        const int row = bm + ty * 8 + i;
        float2 p0 = unpack2(acc[i][0]);
        float2 p1 = unpack2(acc[i][1]);
        float2 p2 = unpack2(acc[i][2]);
        float2 p3 = unpack2(acc[i][3]);
        float4 o0 = make_float4(p0.x + bv[0], p0.y + bv[1], p1.x + bv[2], p1.y + bv[3]);
        float4 o1 = make_float4(p2.x + bv[4], p2.y + bv[5], p3.x + bv[6], p3.y + bv[7]);
        float* cp = C + (size_t)row * N + bn + tx * 8;
        *(float4*)cp = o0;
        *(float4*)(cp + 4) = o1;
    }
}

// ---------------- banded local attention (flash-style, warp per query) ----------------
// grid: (SEQ/8, BATCH*NHEAD, 2); 256 threads = 8 warps.
__global__ void attn_kernel(const float* __restrict__ rel_l)
{
    const int dir = blockIdx.z;
    const int bh = blockIdx.y;
    const int b = bh >> 3;
    const int h = bh & 7;
    const int w = threadIdx.x >> 5;
    const int lane = threadIdx.x & 31;
    const int i = blockIdx.x * 8 + w;

    __shared__ float sbias[WIN];
    if (threadIdx.x < WIN)
        sbias[threadIdx.x] = rel_l[((size_t)dir * NHEAD + h) * WIN + threadIdx.x];
    __syncthreads();

    const size_t dbase = (size_t)dir * TOK * (3 * HID);
    const int tb = b * SEQ;
    const float2 qv = *(const float2*)(g_qkv + dbase + (size_t)(tb + i) * (3 * HID) + h * DK + 2 * lane);

    float m = -1e30f, den = 0.f;
    float2 acc = make_float2(0.f, 0.f);

#pragma unroll 1
    for (int jj = 0; jj < WIN; jj++) {
        const int j = (dir == 0) ? (i - (WIN - 1) + jj) : (i + jj);
        if (j < 0 || j >= SEQ) continue;
        const size_t kbase = dbase + (size_t)(tb + j) * (3 * HID) + h * DK + 2 * lane;
        const float2 kv = *(const float2*)(g_qkv + kbase + HID);
        float p = qv.x * kv.x + qv.y * kv.y;
#pragma unroll
        for (int o = 16; o > 0; o >>= 1) p += __shfl_xor_sync(0xffffffffu, p, o);
        const float s = p * 0.125f + sbias[jj];
        const float mnew = fmaxf(m, s);
        const float sc = __expf(m - mnew);
        const float e  = __expf(s - mnew);
        const float2 vv = *(const float2*)(g_qkv + kbase + 2 * HID);
        den   = den   * sc + e;
        acc.x = acc.x * sc + e * vv.x;
        acc.y = acc.y * sc + e * vv.y;
        m = mnew;
    }
    const float inv = 1.0f / den;
    *(float2*)(g_attn + (size_t)dir * TOK * HID + (size_t)(tb + i) * HID + h * DK + 2 * lane) =
        make_float2(acc.x * inv, acc.y * inv);
}

// ---------------- highway elementwise: y = sig(g)*y + (1-sig(g))*relu(n) ----------------
// grid: (2048, 1, 2); 256 threads; float4 over TOK*HID per dir.
__global__ void highway_elem()
{
    const int dir = blockIdx.z;
    const size_t idx = (size_t)blockIdx.x * blockDim.x + threadIdx.x;  // float4 index
    const size_t t  = idx >> 7;
    const size_t c4 = idx & 127;
    const float* pb = g_proj + (size_t)dir * TOK * 2 * HID + t * 2 * HID;
    const float4 n = *(const float4*)(pb + c4 * 4);
    const float4 g = *(const float4*)(pb + HID + c4 * 4);
    float* yp = g_y + (size_t)dir * TOK * HID + idx * 4;
    float4 y = *(const float4*)yp;
    {
        float s;
        s = 1.f / (1.f + __expf(-g.x)); y.x = s * y.x + (1.f - s) * fmaxf(n.x, 0.f);
        s = 1.f / (1.f + __expf(-g.y)); y.y = s * y.y + (1.f - s) * fmaxf(n.y, 0.f);
        s = 1.f / (1.f + __expf(-g.z)); y.z = s * y.z + (1.f - s) * fmaxf(n.z, 0.f);
        s = 1.f / (1.f + __expf(-g.w)); y.w = s * y.w + (1.f - s) * fmaxf(n.w, 0.f);
    }
    *(float4*)yp = y;
}

// ---------------- residual + state update + concat write ----------------
__global__ void finalize_kernel(float* __restrict__ out_l, int add_res)
{
    const int dir = blockIdx.z;
    const size_t idx = (size_t)blockIdx.x * blockDim.x + threadIdx.x;  // float4 index
    const size_t t  = idx >> 7;
    const size_t c4 = idx & 127;
    float4 v = *(const float4*)(g_y + (size_t)dir * TOK * HID + idx * 4);
    float* stp = g_st + (size_t)dir * TOK * HID + idx * 4;
    if (add_res) {
        const float4 s = *(const float4*)stp;
        v.x += s.x; v.y += s.y; v.z += s.z; v.w += s.w;
    }
    *(float4*)stp = v;
    *(float4*)(out_l + t * (2 * HID) + (size_t)dir * HID + c4 * 4) = v;
}

// ---------------- init: st[fwd] = st[bwd] = inputs ----------------
__global__ void init_state(const float* __restrict__ in)
{
    const size_t idx = (size_t)blockIdx.x * blockDim.x + threadIdx.x;  // float4 index
    const float4 v = *(const float4*)(in + idx * 4);
    *(float4*)(g_st + idx * 4) = v;
    *(float4*)(g_st + (size_t)TOK * HID + idx * 4) = v;
}

// ---------------- launch ----------------
extern "C" void kernel_launch(void* const* d_in, const int* in_sizes, int n_in,
                              void* d_out, int out_size)
{
    const float* inputs = (const float*)d_in[0];
    const float* qkv_w  = (const float*)d_in[2];
    const float* qkv_b  = (const float*)d_in[3];
    const float* rel    = (const float*)d_in[4];
    const float* hw_w   = (const float*)d_in[5];
    const float* hw_b   = (const float*)d_in[6];
    float* out = (float*)d_out;

    float *st, *qkv, *att, *y, *proj;
    cudaGetSymbolAddress((void**)&st,  g_st);
    cudaGetSymbolAddress((void**)&qkv, g_qkv);
    cudaGetSymbolAddress((void**)&att, g_attn);
    cudaGetSymbolAddress((void**)&y,   g_y);
    cudaGetSymbolAddress((void**)&proj, g_proj);

    init_state<<<2048, 256>>>(inputs);

    for (int l = 0; l < 2; l++) {
        const float* qw = qkv_w + (size_t)l * 2 * 4 * HID * HID;
        const float* qb = qkv_b + (size_t)l * 2 * 4 * HID;
        const float* rl = rel   + (size_t)l * 2 * NHEAD * WIN;
        const float* ww = hw_w  + (size_t)l * 2 * 2 * 2 * HID * HID;   // [2dir][2hw][1024][512]
        const float* wb = hw_b  + (size_t)l * 2 * 2 * 2 * HID;

        // fused QKV: [4096,512] x [1536,512]^T
        sgemm_bias<<<dim3(12, 32, 2), 256>>>(st, qw, qb, qkv, 3 * HID,
            (size_t)TOK * HID, (size_t)4 * HID * HID, (size_t)4 * HID, (size_t)TOK * 3 * HID);

        // banded attention
        attn_kernel<<<dim3(SEQ / 8, BATCH * NHEAD, 2), 256>>>(rl);

        // output projection
        sgemm_bias<<<dim3(4, 32, 2), 256>>>(att, qw + (size_t)3 * HID * HID, qb + 3 * HID, y, HID,
            (size_t)TOK * HID, (size_t)4 * HID * HID, (size_t)4 * HID, (size_t)TOK * HID);

        // highway x2
        for (int k = 0; k < 2; k++) {
            sgemm_bias<<<dim3(8, 32, 2), 256>>>(y, ww + (size_t)k * 2 * HID * HID,
                wb + (size_t)k * 2 * HID, proj, 2 * HID,
                (size_t)TOK * HID, (size_t)2 * 2 * HID * HID, (size_t)2 * 2 * HID,
                (size_t)TOK * 2 * HID);
            highway_elem<<<dim3(2048, 1, 2), 256>>>();
        }

        finalize_kernel<<<dim3(2048, 1, 2), 256>>>(out + (size_t)l * TOK * 2 * HID, l > 0 ? 1 : 0);
    }
}

// round 3
// speedup vs baseline: 2.0020x; 2.0020x over previous
#include <cuda_runtime.h>
#include <cuda_bf16.h>
#include <cstdint>
#include <cstddef>

#define NHEAD 8
#define HID 512
#define DK 64
#define SEQ 1024
#define BATCH 4
#define TOK 4096
#define WIN 34
#define KDIM 512

#define BK 32
#define LDS_ROW 80                    // bytes per smem row (64B data + 16B pad)
#define TILE_BYTES (128 * LDS_ROW)    // 10240
#define STAGE_BYTES (4 * TILE_BYTES)  // 40960
#define GSMEM (2 * STAGE_BYTES)       // 81920

// ---------------- scratch (static device arrays; no allocations) ----------------
__device__ float g_st  [2ull * TOK * HID];
__device__ float g_qkv [2ull * TOK * 3 * HID];
__device__ float g_y   [2ull * TOK * HID];
__device__ float g_proj[2ull * TOK * 2 * HID];
__device__ __nv_bfloat16 g_act_hi [2ull * TOK * HID];   // QKV gemm input split
__device__ __nv_bfloat16 g_act_lo [2ull * TOK * HID];
__device__ __nv_bfloat16 g_attn_hi[2ull * TOK * HID];   // attention output split
__device__ __nv_bfloat16 g_attn_lo[2ull * TOK * HID];
__device__ __nv_bfloat16 g_yhi    [2ull * TOK * HID];   // highway input split
__device__ __nv_bfloat16 g_ylo    [2ull * TOK * HID];
__device__ __nv_bfloat16 g_wqkv_hi[4194304];
__device__ __nv_bfloat16 g_wqkv_lo[4194304];
__device__ __nv_bfloat16 g_whw_hi [4194304];
__device__ __nv_bfloat16 g_whw_lo [4194304];

// ---------------- helpers ----------------
__device__ __forceinline__ uint32_t s2u(const void* p) {
    uint32_t a;
    asm("{ .reg .u64 t; cvta.to.shared.u64 t, %1; cvt.u32.u64 %0, t; }" : "=r"(a) : "l"(p));
    return a;
}
__device__ __forceinline__ void cpasync16(uint32_t dst, const void* src) {
    asm volatile("cp.async.cg.shared.global [%0], [%1], 16;" :: "r"(dst), "l"(src));
}
__device__ __forceinline__ void ldmx4(uint32_t* d, uint32_t a) {
    asm volatile("ldmatrix.sync.aligned.m8n8.x4.shared.b16 {%0,%1,%2,%3}, [%4];"
        : "=r"(d[0]), "=r"(d[1]), "=r"(d[2]), "=r"(d[3]) : "r"(a));
}
__device__ __forceinline__ void mma16816(float* c, const uint32_t* a, const uint32_t* b) {
    asm volatile("mma.sync.aligned.m16n8k16.row.col.f32.bf16.bf16.f32 "
        "{%0,%1,%2,%3}, {%4,%5,%6,%7}, {%8,%9}, {%0,%1,%2,%3};"
        : "+f"(c[0]), "+f"(c[1]), "+f"(c[2]), "+f"(c[3])
        : "r"(a[0]), "r"(a[1]), "r"(a[2]), "r"(a[3]), "r"(b[0]), "r"(b[1]));
}
__device__ __forceinline__ uint32_t pack_bf2(float x, float y) {
    __nv_bfloat162 t = __floats2bfloat162_rn(x, y);
    return *(uint32_t*)&t;
}
__device__ __forceinline__ void split1(float v, float& hi, float& lo) {
    __nv_bfloat16 h = __float2bfloat16(v);
    hi = __bfloat162float(h);
    lo = v - hi;
}

// ---------------- fp32 -> (bf16 hi, bf16 lo) for weights ----------------
__global__ void conv_split(const float* __restrict__ src,
                           __nv_bfloat16* __restrict__ hi,
                           __nv_bfloat16* __restrict__ lo)
{
    const size_t i = (size_t)blockIdx.x * blockDim.x + threadIdx.x;
    float4 v = ((const float4*)src)[i];
    float f[4] = {v.x, v.y, v.z, v.w};
    __nv_bfloat16 h[4], l[4];
#pragma unroll
    for (int k = 0; k < 4; k++) {
        h[k] = __float2bfloat16(f[k]);
        l[k] = __float2bfloat16(f[k] - __bfloat162float(h[k]));
    }
    *(uint2*)(hi + 4 * i) = *(uint2*)h;
    *(uint2*)(lo + 4 * i) = *(uint2*)l;
}

// ---------------- HMMA GEMM: C[M,N] = A[M,512] @ B[N,512]^T + bias ----------------
// split-bf16 3-pass via mma.sync m16n8k16.  grid: (N/128, 32, 2); 256 thr.
__global__ __launch_bounds__(256)
void gemm_hmma(const __nv_bfloat16* __restrict__ Ahi, const __nv_bfloat16* __restrict__ Alo,
               const __nv_bfloat16* __restrict__ Bhi, const __nv_bfloat16* __restrict__ Blo,
               const float* __restrict__ bias, float* __restrict__ C,
               __nv_bfloat16* __restrict__ Chi, __nv_bfloat16* __restrict__ Clo,
               int N, size_t sB, size_t sbias, size_t sC)
{
    extern __shared__ char smem[];
    const uint32_t sbase = s2u(smem);
    const int tid = threadIdx.x, lane = tid & 31, wid = tid >> 5;
    const int wm = wid & 1, wn = wid >> 1;
    const int dir = blockIdx.z;
    const int bm = blockIdx.y * 128, bn = blockIdx.x * 128;
    Ahi += (size_t)dir * TOK * KDIM; Alo += (size_t)dir * TOK * KDIM;
    Bhi += (size_t)dir * sB;         Blo += (size_t)dir * sB;
    bias += (size_t)dir * sbias;     C += (size_t)dir * sC;
    if (Chi) { Chi += (size_t)dir * sC; Clo += (size_t)dir * sC; }

    // cp.async coords: thread covers row r, two 16B chunks c0,c0+1 per array
    const int r  = tid >> 1;
    const int c0 = (tid & 1) * 2;
    const uint32_t sro = (uint32_t)r * LDS_ROW + c0 * 16;

    // ldmatrix lane offsets
    const int m8 = lane >> 3, l7 = lane & 7;
    const uint32_t aoff = (uint32_t)(wm * 64 + (m8 & 1) * 8 + l7) * LDS_ROW + (m8 >> 1) * 16;
    const uint32_t boff = (uint32_t)(wn * 32 + (m8 >> 1) * 8 + l7) * LDS_ROW + (m8 & 1) * 16;

    float acc[4][4][4];
#pragma unroll
    for (int i = 0; i < 4; i++)
#pragma unroll
        for (int j = 0; j < 4; j++)
#pragma unroll
            for (int k = 0; k < 4; k++) acc[i][j][k] = 0.f;

#define LOAD_CHUNK(ch, stg) do {                                                  \
        const uint32_t _sb = sbase + (stg) * STAGE_BYTES;                         \
        const int _kof = (ch) * BK + c0 * 8;                                      \
        const size_t _ga = (size_t)(bm + r) * KDIM + _kof;                        \
        const size_t _gb = (size_t)(bn + r) * KDIM + _kof;                        \
        const uint32_t _sa = _sb + sro;                                           \
        cpasync16(_sa,                      Ahi + _ga);                           \
        cpasync16(_sa + 16,                 Ahi + _ga + 8);                       \
        cpasync16(_sa + TILE_BYTES,         Alo + _ga);                           \
        cpasync16(_sa + TILE_BYTES + 16,    Alo + _ga + 8);                       \
        cpasync16(_sa + 2 * TILE_BYTES,     Bhi + _gb);                           \
        cpasync16(_sa + 2 * TILE_BYTES + 16, Bhi + _gb + 8);                      \
        cpasync16(_sa + 3 * TILE_BYTES,     Blo + _gb);                           \
        cpasync16(_sa + 3 * TILE_BYTES + 16, Blo + _gb + 8);                      \
        asm volatile("cp.async.commit_group;" ::: "memory");                      \
    } while (0)

    LOAD_CHUNK(0, 0);

#pragma unroll 1
    for (int ch = 0; ch < 16; ch++) {
        if (ch < 15) {
            LOAD_CHUNK(ch + 1, (ch + 1) & 1);
            asm volatile("cp.async.wait_group 1;" ::: "memory");
        } else {
            asm volatile("cp.async.wait_group 0;" ::: "memory");
        }
        __syncthreads();

        const uint32_t sb = sbase + (ch & 1) * STAGE_BYTES;
#pragma unroll
        for (int kk = 0; kk < 2; kk++) {
            uint32_t ah[4][4], al[4][4], bh[2][4], bl[2][4];
#pragma unroll
            for (int mi = 0; mi < 4; mi++) {
                ldmx4(ah[mi], sb + aoff + mi * (16 * LDS_ROW) + kk * 32);
                ldmx4(al[mi], sb + TILE_BYTES + aoff + mi * (16 * LDS_ROW) + kk * 32);
            }
#pragma unroll
            for (int nj = 0; nj < 2; nj++) {
                ldmx4(bh[nj], sb + 2 * TILE_BYTES + boff + nj * (16 * LDS_ROW) + kk * 32);
                ldmx4(bl[nj], sb + 3 * TILE_BYTES + boff + nj * (16 * LDS_ROW) + kk * 32);
            }
#pragma unroll
            for (int mi = 0; mi < 4; mi++)
#pragma unroll
                for (int ni = 0; ni < 4; ni++) {
                    const uint32_t* fh = &bh[ni >> 1][(ni & 1) * 2];
                    const uint32_t* fl = &bl[ni >> 1][(ni & 1) * 2];
                    mma16816(acc[mi][ni], ah[mi], fh);
                    mma16816(acc[mi][ni], ah[mi], fl);
                    mma16816(acc[mi][ni], al[mi], fh);
                }
        }
        __syncthreads();
    }

    // epilogue
    const int gr = lane >> 2, gc = (lane & 3) * 2;
#pragma unroll
    for (int mi = 0; mi < 4; mi++) {
#pragma unroll
        for (int ni = 0; ni < 4; ni++) {
            const int row0 = bm + wm * 64 + mi * 16 + gr;
            const int col  = bn + wn * 32 + ni * 8 + gc;
            const float b0 = bias[col], b1 = bias[col + 1];
            const float v00 = acc[mi][ni][0] + b0, v01 = acc[mi][ni][1] + b1;
            const float v10 = acc[mi][ni][2] + b0, v11 = acc[mi][ni][3] + b1;
            *(float2*)&C[(size_t)row0 * N + col]       = make_float2(v00, v01);
            *(float2*)&C[(size_t)(row0 + 8) * N + col] = make_float2(v10, v11);
            if (Chi) {
                float h0, l0, h1, l1;
                split1(v00, h0, l0); split1(v01, h1, l1);
                *(uint32_t*)&Chi[(size_t)row0 * N + col] = pack_bf2(h0, h1);
                *(uint32_t*)&Clo[(size_t)row0 * N + col] = pack_bf2(l0, l1);
                split1(v10, h0, l0); split1(v11, h1, l1);
                *(uint32_t*)&Chi[(size_t)(row0 + 8) * N + col] = pack_bf2(h0, h1);
                *(uint32_t*)&Clo[(size_t)(row0 + 8) * N + col] = pack_bf2(l0, l1);
            }
        }
    }
#undef LOAD_CHUNK
}

// ---------------- banded local attention (flash-style, warp per query) ----------------
__global__ void attn_kernel(const float* __restrict__ rel_l)
{
    const int dir = blockIdx.z;
    const int bh = blockIdx.y;
    const int b = bh >> 3;
    const int h = bh & 7;
    const int w = threadIdx.x >> 5;
    const int lane = threadIdx.x & 31;
    const int i = blockIdx.x * 8 + w;

    __shared__ float sbias[WIN];
    if (threadIdx.x < WIN)
        sbias[threadIdx.x] = rel_l[((size_t)dir * NHEAD + h) * WIN + threadIdx.x];
    __syncthreads();

    const size_t dbase = (size_t)dir * TOK * (3 * HID);
    const int tb = b * SEQ;
    const float2 qv = *(const float2*)(g_qkv + dbase + (size_t)(tb + i) * (3 * HID) + h * DK + 2 * lane);

    float m = -1e30f, den = 0.f;
    float2 acc = make_float2(0.f, 0.f);

#pragma unroll 1
    for (int jj = 0; jj < WIN; jj++) {
        const int j = (dir == 0) ? (i - (WIN - 1) + jj) : (i + jj);
        if (j < 0 || j >= SEQ) continue;
        const size_t kbase = dbase + (size_t)(tb + j) * (3 * HID) + h * DK + 2 * lane;
        const float2 kv = *(const float2*)(g_qkv + kbase + HID);
        float p = qv.x * kv.x + qv.y * kv.y;
#pragma unroll
        for (int o = 16; o > 0; o >>= 1) p += __shfl_xor_sync(0xffffffffu, p, o);
        const float s = p * 0.125f + sbias[jj];
        const float mnew = fmaxf(m, s);
        const float sc = __expf(m - mnew);
        const float e  = __expf(s - mnew);
        const float2 vv = *(const float2*)(g_qkv + kbase + 2 * HID);
        den   = den   * sc + e;
        acc.x = acc.x * sc + e * vv.x;
        acc.y = acc.y * sc + e * vv.y;
        m = mnew;
    }
    const float inv = 1.0f / den;
    const float ox = acc.x * inv, oy = acc.y * inv;
    float h0, l0, h1, l1;
    split1(ox, h0, l0); split1(oy, h1, l1);
    const size_t oidx = (size_t)dir * TOK * HID + (size_t)(tb + i) * HID + h * DK + 2 * lane;
    *(uint32_t*)&g_attn_hi[oidx] = pack_bf2(h0, h1);
    *(uint32_t*)&g_attn_lo[oidx] = pack_bf2(l0, l1);
}

// ---------------- highway elementwise (+ emit bf16 split of y) ----------------
__global__ void highway_elem()
{
    const int dir = blockIdx.z;
    const size_t idx = (size_t)blockIdx.x * blockDim.x + threadIdx.x;
    const size_t t  = idx >> 7;
    const size_t c4 = idx & 127;
    const float* pb = g_proj + (size_t)dir * TOK * 2 * HID + t * 2 * HID;
    const float4 n = *(const float4*)(pb + c4 * 4);
    const float4 g = *(const float4*)(pb + HID + c4 * 4);
    float* yp = g_y + (size_t)dir * TOK * HID + idx * 4;
    float4 y = *(const float4*)yp;
    float s;
    s = 1.f / (1.f + __expf(-g.x)); y.x = s * y.x + (1.f - s) * fmaxf(n.x, 0.f);
    s = 1.f / (1.f + __expf(-g.y)); y.y = s * y.y + (1.f - s) * fmaxf(n.y, 0.f);
    s = 1.f / (1.f + __expf(-g.z)); y.z = s * y.z + (1.f - s) * fmaxf(n.z, 0.f);
    s = 1.f / (1.f + __expf(-g.w)); y.w = s * y.w + (1.f - s) * fmaxf(n.w, 0.f);
    *(float4*)yp = y;
    float h[4], l[4];
    split1(y.x, h[0], l[0]); split1(y.y, h[1], l[1]);
    split1(y.z, h[2], l[2]); split1(y.w, h[3], l[3]);
    uint2 ph = make_uint2(pack_bf2(h[0], h[1]), pack_bf2(h[2], h[3]));
    uint2 pl = make_uint2(pack_bf2(l[0], l[1]), pack_bf2(l[2], l[3]));
    *(uint2*)&g_yhi[(size_t)dir * TOK * HID + idx * 4] = ph;
    *(uint2*)&g_ylo[(size_t)dir * TOK * HID + idx * 4] = pl;
}

// ---------------- residual + state + concat (+ emit bf16 split of st) ----------------
__global__ void finalize_kernel(float* __restrict__ out_l, int add_res)
{
    const int dir = blockIdx.z;
    const size_t idx = (size_t)blockIdx.x * blockDim.x + threadIdx.x;
    const size_t t  = idx >> 7;
    const size_t c4 = idx & 127;
    float4 v = *(const float4*)(g_y + (size_t)dir * TOK * HID + idx * 4);
    float* stp = g_st + (size_t)dir * TOK * HID + idx * 4;
    if (add_res) {
        const float4 s = *(const float4*)stp;
        v.x += s.x; v.y += s.y; v.z += s.z; v.w += s.w;
    }
    *(float4*)stp = v;
    *(float4*)(out_l + t * (2 * HID) + (size_t)dir * HID + c4 * 4) = v;
    float h[4], l[4];
    split1(v.x, h[0], l[0]); split1(v.y, h[1], l[1]);
    split1(v.z, h[2], l[2]); split1(v.w, h[3], l[3]);
    *(uint2*)&g_act_hi[(size_t)dir * TOK * HID + idx * 4] =
        make_uint2(pack_bf2(h[0], h[1]), pack_bf2(h[2], h[3]));
    *(uint2*)&g_act_lo[(size_t)dir * TOK * HID + idx * 4] =
        make_uint2(pack_bf2(l[0], l[1]), pack_bf2(l[2], l[3]));
}

// ---------------- init: st = inputs (both dirs) + act split ----------------
__global__ void init_state(const float* __restrict__ in)
{
    const size_t idx = (size_t)blockIdx.x * blockDim.x + threadIdx.x;
    const float4 v = *(const float4*)(in + idx * 4);
    *(float4*)(g_st + idx * 4) = v;
    *(float4*)(g_st + (size_t)TOK * HID + idx * 4) = v;
    float h[4], l[4];
    split1(v.x, h[0], l[0]); split1(v.y, h[1], l[1]);
    split1(v.z, h[2], l[2]); split1(v.w, h[3], l[3]);
    const uint2 ph = make_uint2(pack_bf2(h[0], h[1]), pack_bf2(h[2], h[3]));
    const uint2 pl = make_uint2(pack_bf2(l[0], l[1]), pack_bf2(l[2], l[3]));
    *(uint2*)&g_act_hi[idx * 4] = ph;
    *(uint2*)&g_act_lo[idx * 4] = pl;
    *(uint2*)&g_act_hi[(size_t)TOK * HID + idx * 4] = ph;
    *(uint2*)&g_act_lo[(size_t)TOK * HID + idx * 4] = pl;
}

// ---------------- launch ----------------
extern "C" void kernel_launch(void* const* d_in, const int* in_sizes, int n_in,
                              void* d_out, int out_size)
{
    const float* inputs = (const float*)d_in[0];
    const float* qkv_w  = (const float*)d_in[2];
    const float* qkv_b  = (const float*)d_in[3];
    const float* rel    = (const float*)d_in[4];
    const float* hw_w   = (const float*)d_in[5];
    const float* hw_b   = (const float*)d_in[6];
    float* out = (float*)d_out;

    float *qkvp, *yv;
    __nv_bfloat16 *ahi, *alo, *athi, *atlo, *yhi, *ylo, *wqh, *wql, *whh, *whl;
    cudaGetSymbolAddress((void**)&qkvp, g_qkv);
    cudaGetSymbolAddress((void**)&yv,   g_y);
    cudaGetSymbolAddress((void**)&ahi,  g_act_hi);
    cudaGetSymbolAddress((void**)&alo,  g_act_lo);
    cudaGetSymbolAddress((void**)&athi, g_attn_hi);
    cudaGetSymbolAddress((void**)&atlo, g_attn_lo);
    cudaGetSymbolAddress((void**)&yhi,  g_yhi);
    cudaGetSymbolAddress((void**)&ylo,  g_ylo);
    cudaGetSymbolAddress((void**)&wqh,  g_wqkv_hi);
    cudaGetSymbolAddress((void**)&wql,  g_wqkv_lo);
    cudaGetSymbolAddress((void**)&whh,  g_whw_hi);
    cudaGetSymbolAddress((void**)&whl,  g_whw_lo);
    float* proj; cudaGetSymbolAddress((void**)&proj, g_proj);

    cudaFuncSetAttribute(gemm_hmma, cudaFuncAttributeMaxDynamicSharedMemorySize, GSMEM);

    conv_split<<<4096, 256>>>(qkv_w, wqh, wql);
    conv_split<<<4096, 256>>>(hw_w,  whh, whl);
    init_state<<<2048, 256>>>(inputs);

    for (int l = 0; l < 2; l++) {
        const size_t QL = (size_t)l * 2 * 4 * HID * HID;
        const size_t HL = (size_t)l * 2 * 2 * 2 * HID * HID;

        // fused QKV: [4096,512] x [1536,512]^T  -> fp32 qkv
        gemm_hmma<<<dim3(12, 32, 2), 256, GSMEM>>>(
            ahi, alo, wqh + QL, wql + QL,
            qkv_b + (size_t)l * 2 * 4 * HID, qkvp, nullptr, nullptr, 3 * HID,
            (size_t)4 * HID * HID, (size_t)4 * HID, (size_t)TOK * 3 * HID);

        attn_kernel<<<dim3(SEQ / 8, BATCH * NHEAD, 2), 256>>>(rel + (size_t)l * 2 * NHEAD * WIN);

        // out projection -> y fp32 + y split
        gemm_hmma<<<dim3(4, 32, 2), 256, GSMEM>>>(
            athi, atlo, wqh + QL + (size_t)3 * HID * HID, wql + QL + (size_t)3 * HID * HID,
            qkv_b + (size_t)l * 2 * 4 * HID + 3 * HID, yv, yhi, ylo, HID,
            (size_t)4 * HID * HID, (size_t)4 * HID, (size_t)TOK * HID);

        // highway x2
        for (int k = 0; k < 2; k++) {
            gemm_hmma<<<dim3(8, 32, 2), 256, GSMEM>>>(
                yhi, ylo, whh + HL + (size_t)k * 2 * HID * HID, whl + HL + (size_t)k * 2 * HID * HID,
                hw_b + (size_t)l * 2 * 2 * 2 * HID + (size_t)k * 2 * HID, proj, nullptr, nullptr,
                2 * HID, (size_t)2 * 2 * HID * HID, (size_t)2 * 2 * HID, (size_t)TOK * 2 * HID);
            highway_elem<<<dim3(2048, 1, 2), 256>>>();
        }

        finalize_kernel<<<dim3(2048, 1, 2), 256>>>(out + (size_t)l * TOK * 2 * HID, l > 0 ? 1 : 0);
    }
}

// round 4
// speedup vs baseline: 2.0683x; 1.0331x over previous
#include <cuda_runtime.h>
#include <cuda_bf16.h>
#include <cstdint>
#include <cstddef>

#define NHEAD 8
#define HID 512
#define DK 64
#define SEQ 1024
#define BATCH 4
#define TOK 4096
#define WIN 34
#define KDIM 512

#define BK 32
#define TILE_B 8192                    // 128 rows * 64B
#define STAGE_B (4 * TILE_B)           // 32768: Ahi|Alo|Bhi|Blo
#define GSMEM (3 * STAGE_B)            // 98304

// ---------------- scratch ----------------
__device__ float g_st  [2ull * TOK * HID];
__device__ float g_qkv [2ull * TOK * 3 * HID];
__device__ float g_y   [2ull * TOK * HID];
__device__ __nv_bfloat16 g_act_hi [2ull * TOK * HID];
__device__ __nv_bfloat16 g_act_lo [2ull * TOK * HID];
__device__ __nv_bfloat16 g_attn_hi[2ull * TOK * HID];
__device__ __nv_bfloat16 g_attn_lo[2ull * TOK * HID];
__device__ __nv_bfloat16 g_yhi    [2ull * TOK * HID];
__device__ __nv_bfloat16 g_ylo    [2ull * TOK * HID];
__device__ __nv_bfloat16 g_y2hi   [2ull * TOK * HID];
__device__ __nv_bfloat16 g_y2lo   [2ull * TOK * HID];
__device__ __nv_bfloat16 g_wqkv_hi[4194304];
__device__ __nv_bfloat16 g_wqkv_lo[4194304];
__device__ __nv_bfloat16 g_whw_hi [4194304];
__device__ __nv_bfloat16 g_whw_lo [4194304];

// ---------------- helpers ----------------
__device__ __forceinline__ uint32_t s2u(const void* p) {
    uint32_t a;
    asm("{ .reg .u64 t; cvta.to.shared.u64 t, %1; cvt.u32.u64 %0, t; }" : "=r"(a) : "l"(p));
    return a;
}
__device__ __forceinline__ void cpasync16(uint32_t dst, const void* src) {
    asm volatile("cp.async.cg.shared.global [%0], [%1], 16;" :: "r"(dst), "l"(src));
}
__device__ __forceinline__ void ldmx4(uint32_t* d, uint32_t a) {
    asm volatile("ldmatrix.sync.aligned.m8n8.x4.shared.b16 {%0,%1,%2,%3}, [%4];"
        : "=r"(d[0]), "=r"(d[1]), "=r"(d[2]), "=r"(d[3]) : "r"(a));
}
__device__ __forceinline__ void mma16816(float* c, const uint32_t* a, const uint32_t* b) {
    asm volatile("mma.sync.aligned.m16n8k16.row.col.f32.bf16.bf16.f32 "
        "{%0,%1,%2,%3}, {%4,%5,%6,%7}, {%8,%9}, {%0,%1,%2,%3};"
        : "+f"(c[0]), "+f"(c[1]), "+f"(c[2]), "+f"(c[3])
        : "r"(a[0]), "r"(a[1]), "r"(a[2]), "r"(a[3]), "r"(b[0]), "r"(b[1]));
}
__device__ __forceinline__ uint32_t pack_bf2(float x, float y) {
    __nv_bfloat162 t = __floats2bfloat162_rn(x, y);
    return *(uint32_t*)&t;
}
__device__ __forceinline__ void split1(float v, float& hi, float& lo) {
    __nv_bfloat16 h = __float2bfloat16(v);
    hi = __bfloat162float(h);
    lo = v - hi;
}

// ---------------- weight conversions ----------------
__global__ void conv_split(const float* __restrict__ src,
                           __nv_bfloat16* __restrict__ hi,
                           __nv_bfloat16* __restrict__ lo)
{
    const size_t i = (size_t)blockIdx.x * blockDim.x + threadIdx.x;
    float4 v = ((const float4*)src)[i];
    float f[4] = {v.x, v.y, v.z, v.w};
    __nv_bfloat16 h[4], l[4];
#pragma unroll
    for (int k = 0; k < 4; k++) {
        h[k] = __float2bfloat16(f[k]);
        l[k] = __float2bfloat16(f[k] - __bfloat162float(h[k]));
    }
    *(uint2*)(hi + 4 * i) = *(uint2*)h;
    *(uint2*)(lo + 4 * i) = *(uint2*)l;
}

// highway weights: interleave rows so out col 2j=nonlin_j, 2j+1=gate_j
__global__ void conv_hw(const float* __restrict__ src,
                        __nv_bfloat16* __restrict__ hi,
                        __nv_bfloat16* __restrict__ lo)
{
    const size_t idx = (size_t)blockIdx.x * blockDim.x + threadIdx.x; // float4 id
    const size_t m   = idx >> 17;           // matrix (1024x512 = 131072 float4)
    const size_t rem = idx & 131071;
    const int    r   = (int)(rem >> 7);
    const size_t c4  = rem & 127;
    const int dr = (r < 512) ? (2 * r) : (2 * (r - 512) + 1);
    float4 v = ((const float4*)src)[idx];
    float f[4] = {v.x, v.y, v.z, v.w};
    __nv_bfloat16 h[4], l[4];
#pragma unroll
    for (int k = 0; k < 4; k++) {
        h[k] = __float2bfloat16(f[k]);
        l[k] = __float2bfloat16(f[k] - __bfloat162float(h[k]));
    }
    const size_t dst = (m << 17) + (size_t)dr * 128 + c4;
    *(uint2*)(hi + 4 * dst) = *(uint2*)h;
    *(uint2*)(lo + 4 * dst) = *(uint2*)l;
}

// ---------------- fused HMMA GEMM ----------------
// C[M,N] = A[M,512] @ B[N,512]^T + bias  (split-bf16 3-pass)
// mode 0: write C fp32
// mode 1: write C fp32 + bf16 split to Shi/Slo
// mode 2: highway mid: y' = sig(g)*y + (1-sig)*relu(n); write Yv + split Shi/Slo
// mode 3: highway final: v = y' (+ St if add_res); St=v, Out=v, split Shi/Slo
__global__ __launch_bounds__(256)
void gemm_fused(const __nv_bfloat16* __restrict__ Ahi, const __nv_bfloat16* __restrict__ Alo,
                const __nv_bfloat16* __restrict__ Bhi, const __nv_bfloat16* __restrict__ Blo,
                const float* __restrict__ bias, float* __restrict__ C,
                __nv_bfloat16* __restrict__ Shi, __nv_bfloat16* __restrict__ Slo,
                float* __restrict__ Yv, float* __restrict__ St, float* __restrict__ Out,
                int N, size_t sB, size_t sbias, size_t sC, int mode, int add_res)
{
    extern __shared__ char smem[];
    const uint32_t sbase = s2u(smem);
    const int tid = threadIdx.x, lane = tid & 31, wid = tid >> 5;
    const int wm = wid & 1, wn = wid >> 1;
    const int dir = blockIdx.z;
    const int bm = blockIdx.y * 128, bn = blockIdx.x * 128;
    Ahi += (size_t)dir * TOK * KDIM; Alo += (size_t)dir * TOK * KDIM;
    Bhi += (size_t)dir * sB;         Blo += (size_t)dir * sB;
    bias += (size_t)dir * sbias;

    // cp.async store coords (swizzled 64B rows)
    const int r  = tid >> 1;
    const int c0 = (tid & 1) * 2;
    const uint32_t xst = (uint32_t)((r >> 1) & 3);
    const uint32_t sro0 = (uint32_t)r * 64 + (((uint32_t)c0 ^ xst) << 4);
    const uint32_t sro1 = (uint32_t)r * 64 + ((((uint32_t)c0 + 1) ^ xst) << 4);

    // ldmatrix coords
    const int m8 = lane >> 3, l7 = lane & 7;
    const uint32_t xm = (uint32_t)((l7 >> 1) & 3);
    const uint32_t a_base = (uint32_t)(wm * 64 + (m8 & 1) * 8 + l7) * 64;
    const uint32_t b_base = (uint32_t)(wn * 32 + (m8 >> 1) * 8 + l7) * 64;
    const uint32_t a_c = (((uint32_t)(m8 >> 1)) ^ (xm & 1)) << 4;
    const uint32_t b_c = (((uint32_t)(m8 & 1)) ^ (xm & 1)) << 4;
    const uint32_t kof[2] = { (xm & 2) << 4, (2u ^ (xm & 2)) << 4 };

    float acc[4][4][4];
#pragma unroll
    for (int i = 0; i < 4; i++)
#pragma unroll
        for (int j = 0; j < 4; j++)
#pragma unroll
            for (int k = 0; k < 4; k++) acc[i][j][k] = 0.f;

#define LOAD_CHUNK(ch, stg) do {                                                   \
        const uint32_t _sb = sbase + (uint32_t)(stg) * STAGE_B;                    \
        const int _ke = (ch) * BK + c0 * 8;                                        \
        const size_t _ga = (size_t)(bm + r) * KDIM + _ke;                          \
        const size_t _gb = (size_t)(bn + r) * KDIM + _ke;                          \
        cpasync16(_sb + sro0,              Ahi + _ga);                             \
        cpasync16(_sb + sro1,              Ahi + _ga + 8);                         \
        cpasync16(_sb + TILE_B + sro0,     Alo + _ga);                             \
        cpasync16(_sb + TILE_B + sro1,     Alo + _ga + 8);                         \
        cpasync16(_sb + 2 * TILE_B + sro0, Bhi + _gb);                             \
        cpasync16(_sb + 2 * TILE_B + sro1, Bhi + _gb + 8);                         \
        cpasync16(_sb + 3 * TILE_B + sro0, Blo + _gb);                             \
        cpasync16(_sb + 3 * TILE_B + sro1, Blo + _gb + 8);                         \
        asm volatile("cp.async.commit_group;" ::: "memory");                       \
    } while (0)

    LOAD_CHUNK(0, 0);
    LOAD_CHUNK(1, 1);

    int stg_c = 0;   // ch % 3
    int stg_l = 2;   // (ch+2) % 3
#pragma unroll 1
    for (int ch = 0; ch < 16; ch++) {
        if (ch < 15) asm volatile("cp.async.wait_group 1;" ::: "memory");
        else         asm volatile("cp.async.wait_group 0;" ::: "memory");
        __syncthreads();
        if (ch + 2 < 16) LOAD_CHUNK(ch + 2, stg_l);

        const uint32_t sb = sbase + (uint32_t)stg_c * STAGE_B;
#pragma unroll
        for (int kk = 0; kk < 2; kk++) {
            uint32_t ah[4][4], al[4][4], bh[2][4], bl[2][4];
#pragma unroll
            for (int mi = 0; mi < 4; mi++) {
                const uint32_t aa = sb + a_base + mi * 1024 + a_c + kof[kk];
                ldmx4(ah[mi], aa);
                ldmx4(al[mi], aa + TILE_B);
            }
#pragma unroll
            for (int nj = 0; nj < 2; nj++) {
                const uint32_t ba = sb + 2 * TILE_B + b_base + nj * 1024 + b_c + kof[kk];
                ldmx4(bh[nj], ba);
                ldmx4(bl[nj], ba + TILE_B);
            }
#pragma unroll
            for (int mi = 0; mi < 4; mi++)
#pragma unroll
                for (int ni = 0; ni < 4; ni++) {
                    const uint32_t* fh = &bh[ni >> 1][(ni & 1) * 2];
                    const uint32_t* fl = &bl[ni >> 1][(ni & 1) * 2];
                    mma16816(acc[mi][ni], ah[mi], fh);
                    mma16816(acc[mi][ni], ah[mi], fl);
                    mma16816(acc[mi][ni], al[mi], fh);
                }
        }
        stg_c = (stg_c == 2) ? 0 : stg_c + 1;
        stg_l = (stg_l == 2) ? 0 : stg_l + 1;
    }
#undef LOAD_CHUNK

    // ---------------- epilogue ----------------
    const int gr = lane >> 2, gc = (lane & 3) * 2;

    if (mode <= 1) {
        float* Cp = C + (size_t)dir * sC;
        __nv_bfloat16* SH = Shi ? (Shi + (size_t)dir * sC) : nullptr;
        __nv_bfloat16* SL = Slo ? (Slo + (size_t)dir * sC) : nullptr;
#pragma unroll
        for (int mi = 0; mi < 4; mi++) {
#pragma unroll
            for (int ni = 0; ni < 4; ni++) {
                const int row0 = bm + wm * 64 + mi * 16 + gr;
                const int col  = bn + wn * 32 + ni * 8 + gc;
                const float b0 = bias[col], b1 = bias[col + 1];
                const float v00 = acc[mi][ni][0] + b0, v01 = acc[mi][ni][1] + b1;
                const float v10 = acc[mi][ni][2] + b0, v11 = acc[mi][ni][3] + b1;
                *(float2*)&Cp[(size_t)row0 * N + col]       = make_float2(v00, v01);
                *(float2*)&Cp[(size_t)(row0 + 8) * N + col] = make_float2(v10, v11);
                if (mode == 1) {
                    float h0, l0, h1, l1;
                    split1(v00, h0, l0); split1(v01, h1, l1);
                    *(uint32_t*)&SH[(size_t)row0 * N + col] = pack_bf2(h0, h1);
                    *(uint32_t*)&SL[(size_t)row0 * N + col] = pack_bf2(l0, l1);
                    split1(v10, h0, l0); split1(v11, h1, l1);
                    *(uint32_t*)&SH[(size_t)(row0 + 8) * N + col] = pack_bf2(h0, h1);
                    *(uint32_t*)&SL[(size_t)(row0 + 8) * N + col] = pack_bf2(l0, l1);
                }
            }
        }
    } else {
        float* Y = Yv + (size_t)dir * TOK * HID;
        float* S = St + (size_t)dir * TOK * HID;
        __nv_bfloat16* SH = Shi + (size_t)dir * TOK * HID;
        __nv_bfloat16* SL = Slo + (size_t)dir * TOK * HID;
#pragma unroll
        for (int mi = 0; mi < 4; mi++) {
#pragma unroll
            for (int ni = 0; ni < 4; ni++) {
                const int row0 = bm + wm * 64 + mi * 16 + gr;
                const int col  = bn + wn * 32 + ni * 8 + gc;
                const int j    = col >> 1;
                const float bnl = bias[j], bgt = bias[j + HID];
#pragma unroll
                for (int rr = 0; rr < 2; rr++) {
                    const int row = row0 + rr * 8;
                    const float n = acc[mi][ni][rr * 2]     + bnl;
                    const float g = acc[mi][ni][rr * 2 + 1] + bgt;
                    const size_t o = (size_t)row * HID + j;
                    const float yo = Y[o];
                    const float s = 1.f / (1.f + __expf(-g));
                    float v = s * yo + (1.f - s) * fmaxf(n, 0.f);
                    if (mode == 2) {
                        Y[o] = v;
                    } else {
                        if (add_res) v += S[o];
                        S[o] = v;
                        Out[(size_t)row * (2 * HID) + (size_t)dir * HID + j] = v;
                    }
                    float h, l;
                    split1(v, h, l);
                    SH[o] = __float2bfloat16(h);
                    SL[o] = __float2bfloat16(l);
                }
            }
        }
    }
}

// ---------------- banded local attention ----------------
__global__ void attn_kernel(const float* __restrict__ rel_l)
{
    const int dir = blockIdx.z;
    const int bh = blockIdx.y;
    const int b = bh >> 3;
    const int h = bh & 7;
    const int w = threadIdx.x >> 5;
    const int lane = threadIdx.x & 31;
    const int i = blockIdx.x * 8 + w;

    __shared__ float sbias[WIN];
    if (threadIdx.x < WIN)
        sbias[threadIdx.x] = rel_l[((size_t)dir * NHEAD + h) * WIN + threadIdx.x];
    __syncthreads();

    const size_t dbase = (size_t)dir * TOK * (3 * HID);
    const int tb = b * SEQ;
    const float2 qv = *(const float2*)(g_qkv + dbase + (size_t)(tb + i) * (3 * HID) + h * DK + 2 * lane);

    float m = -1e30f, den = 0.f;
    float2 acc = make_float2(0.f, 0.f);

#pragma unroll 1
    for (int jj = 0; jj < WIN; jj++) {
        const int j = (dir == 0) ? (i - (WIN - 1) + jj) : (i + jj);
        if (j < 0 || j >= SEQ) continue;
        const size_t kbase = dbase + (size_t)(tb + j) * (3 * HID) + h * DK + 2 * lane;
        const float2 kv = *(const float2*)(g_qkv + kbase + HID);
        float p = qv.x * kv.x + qv.y * kv.y;
#pragma unroll
        for (int o = 16; o > 0; o >>= 1) p += __shfl_xor_sync(0xffffffffu, p, o);
        const float s = p * 0.125f + sbias[jj];
        const float mnew = fmaxf(m, s);
        const float sc = __expf(m - mnew);
        const float e  = __expf(s - mnew);
        const float2 vv = *(const float2*)(g_qkv + kbase + 2 * HID);
        den   = den   * sc + e;
        acc.x = acc.x * sc + e * vv.x;
        acc.y = acc.y * sc + e * vv.y;
        m = mnew;
    }
    const float inv = 1.0f / den;
    const float ox = acc.x * inv, oy = acc.y * inv;
    float h0, l0, h1, l1;
    split1(ox, h0, l0); split1(oy, h1, l1);
    const size_t oidx = (size_t)dir * TOK * HID + (size_t)(tb + i) * HID + h * DK + 2 * lane;
    *(uint32_t*)&g_attn_hi[oidx] = pack_bf2(h0, h1);
    *(uint32_t*)&g_attn_lo[oidx] = pack_bf2(l0, l1);
}

// ---------------- init: act splits (both dirs) ----------------
__global__ void init_state(const float* __restrict__ in)
{
    const size_t idx = (size_t)blockIdx.x * blockDim.x + threadIdx.x;
    const float4 v = *(const float4*)(in + idx * 4);
    float h[4], l[4];
    split1(v.x, h[0], l[0]); split1(v.y, h[1], l[1]);
    split1(v.z, h[2], l[2]); split1(v.w, h[3], l[3]);
    const uint2 ph = make_uint2(pack_bf2(h[0], h[1]), pack_bf2(h[2], h[3]));
    const uint2 pl = make_uint2(pack_bf2(l[0], l[1]), pack_bf2(l[2], l[3]));
    *(uint2*)&g_act_hi[idx * 4] = ph;
    *(uint2*)&g_act_lo[idx * 4] = pl;
    *(uint2*)&g_act_hi[(size_t)TOK * HID + idx * 4] = ph;
    *(uint2*)&g_act_lo[(size_t)TOK * HID + idx * 4] = pl;
}

// ---------------- launch ----------------
extern "C" void kernel_launch(void* const* d_in, const int* in_sizes, int n_in,
                              void* d_out, int out_size)
{
    const float* inputs = (const float*)d_in[0];
    const float* qkv_w  = (const float*)d_in[2];
    const float* qkv_b  = (const float*)d_in[3];
    const float* rel    = (const float*)d_in[4];
    const float* hw_w   = (const float*)d_in[5];
    const float* hw_b   = (const float*)d_in[6];
    float* out = (float*)d_out;

    float *qkvp, *yv, *st;
    __nv_bfloat16 *ahi, *alo, *athi, *atlo, *yhi, *ylo, *y2hi, *y2lo, *wqh, *wql, *whh, *whl;
    cudaGetSymbolAddress((void**)&qkvp, g_qkv);
    cudaGetSymbolAddress((void**)&yv,   g_y);
    cudaGetSymbolAddress((void**)&st,   g_st);
    cudaGetSymbolAddress((void**)&ahi,  g_act_hi);
    cudaGetSymbolAddress((void**)&alo,  g_act_lo);
    cudaGetSymbolAddress((void**)&athi, g_attn_hi);
    cudaGetSymbolAddress((void**)&atlo, g_attn_lo);
    cudaGetSymbolAddress((void**)&yhi,  g_yhi);
    cudaGetSymbolAddress((void**)&ylo,  g_ylo);
    cudaGetSymbolAddress((void**)&y2hi, g_y2hi);
    cudaGetSymbolAddress((void**)&y2lo, g_y2lo);
    cudaGetSymbolAddress((void**)&wqh,  g_wqkv_hi);
    cudaGetSymbolAddress((void**)&wql,  g_wqkv_lo);
    cudaGetSymbolAddress((void**)&whh,  g_whw_hi);
    cudaGetSymbolAddress((void**)&whl,  g_whw_lo);

    cudaFuncSetAttribute(gemm_fused, cudaFuncAttributeMaxDynamicSharedMemorySize, GSMEM);

    conv_split<<<4096, 256>>>(qkv_w, wqh, wql);
    conv_hw<<<4096, 256>>>(hw_w, whh, whl);
    init_state<<<2048, 256>>>(inputs);

    for (int l = 0; l < 2; l++) {
        const size_t QL = (size_t)l * 2 * 4 * HID * HID;
        const size_t HL = (size_t)l * 2 * 2 * 2 * HID * HID;
        const float* qb = qkv_b + (size_t)l * 2 * 4 * HID;
        const float* hb = hw_b + (size_t)l * 2 * 2 * 2 * HID;

        // QKV: [4096,512] x [1536,512]^T -> fp32 qkv (mode 0)
        gemm_fused<<<dim3(12, 32, 2), 256, GSMEM>>>(
            ahi, alo, wqh + QL, wql + QL, qb, qkvp, nullptr, nullptr,
            nullptr, nullptr, nullptr,
            3 * HID, (size_t)4 * HID * HID, (size_t)4 * HID, (size_t)TOK * 3 * HID, 0, 0);

        attn_kernel<<<dim3(SEQ / 8, BATCH * NHEAD, 2), 256>>>(rel + (size_t)l * 2 * NHEAD * WIN);

        // out projection -> y fp32 + split (mode 1)
        gemm_fused<<<dim3(4, 32, 2), 256, GSMEM>>>(
            athi, atlo, wqh + QL + (size_t)3 * HID * HID, wql + QL + (size_t)3 * HID * HID,
            qb + 3 * HID, yv, yhi, ylo, nullptr, nullptr, nullptr,
            HID, (size_t)4 * HID * HID, (size_t)4 * HID, (size_t)TOK * HID, 1, 0);

        // highway 1 (mode 2): reads yhi/ylo, updates y, writes y2hi/y2lo
        gemm_fused<<<dim3(8, 32, 2), 256, GSMEM>>>(
            yhi, ylo, whh + HL, whl + HL, hb, nullptr, y2hi, y2lo,
            yv, nullptr, nullptr,
            2 * HID, (size_t)2 * 2 * HID * HID, (size_t)2 * 2 * HID, 0, 2, 0);

        // highway 2 (mode 3): reads y2hi/y2lo, residual+state+concat+act split
        gemm_fused<<<dim3(8, 32, 2), 256, GSMEM>>>(
            y2hi, y2lo, whh + HL + (size_t)2 * HID * HID, whl + HL + (size_t)2 * HID * HID,
            hb + 2 * HID, nullptr, ahi, alo,
            yv, st, out + (size_t)l * TOK * 2 * HID,
            2 * HID, (size_t)2 * 2 * HID * HID, (size_t)2 * 2 * HID, 0, 3, l > 0 ? 1 : 0);
    }
}